// round 1
// baseline (speedup 1.0000x reference)
#include <cuda_runtime.h>

#define BB 2
#define SS 4096
#define HH 8
#define DD 64
#define BR 64
#define BC 64
#define ST 68   // smem row stride in floats (pad for bank conflicts, keeps 16B alignment)

__device__ __forceinline__ float ex2f(float x) {
    float y;
    asm("ex2.approx.f32 %0, %1;" : "=f"(y) : "f"(x));
    return y;
}

__global__ __launch_bounds__(256, 2)
void fa_kernel(const float* __restrict__ q,
               const float* __restrict__ k,
               const float* __restrict__ v,
               float* __restrict__ out) {
    extern __shared__ float sm[];
    float* Qt = sm;              // [DD][ST], Qt[d][i] = Q[i][d]
    float* Kt = sm + DD * ST;    // [DD][ST], Kt[d][j] = K[j][d]
    float* Vs = sm + 2 * DD * ST; // [BC][ST], Vs[j][d]
    float* Ps = sm + 3 * DD * ST; // [BR][ST], Ps[i][j]

    const int t  = threadIdx.x;
    const int tx = t & 15;        // 0..15 -> j / d-col group
    const int ty = t >> 4;        // 0..15 -> i group
    const int bh = blockIdx.y;    // b*HH + h
    const int b  = bh >> 3;
    const int h  = bh & 7;
    const int s0 = blockIdx.x * BR;

    const float kScale = 1.44269504088896340736f / 8.0f;  // log2(e)/sqrt(64)

    // ---- load Q tile, transposed into smem ----
    {
        const int ch = t & 15;   // float4 chunk within a 64-float row
        const int i0 = t >> 4;
        #pragma unroll
        for (int rr = 0; rr < 4; rr++) {
            const int i = i0 + rr * 16;
            const float4 f = *reinterpret_cast<const float4*>(
                q + ((size_t)((b * SS + s0 + i) * HH + h)) * DD + ch * 4);
            const int d = ch * 4;
            Qt[(d + 0) * ST + i] = f.x;
            Qt[(d + 1) * ST + i] = f.y;
            Qt[(d + 2) * ST + i] = f.z;
            Qt[(d + 3) * ST + i] = f.w;
        }
    }

    float m[4], l[4], o[4][4];
    #pragma unroll
    for (int r = 0; r < 4; r++) {
        m[r] = -1e30f;
        l[r] = 0.0f;
        #pragma unroll
        for (int c = 0; c < 4; c++) o[r][c] = 0.0f;
    }

    for (int kt = 0; kt < SS / BC; kt++) {
        __syncthreads();   // prev PV done; safe to overwrite Kt/Vs
        // ---- load K (transposed) and V (straight) tiles ----
        {
            const int ch = t & 15;
            const int j0 = t >> 4;
            #pragma unroll
            for (int rr = 0; rr < 4; rr++) {
                const int j = j0 + rr * 16;
                const size_t base =
                    ((size_t)((b * SS + kt * BC + j) * HH + h)) * DD + ch * 4;
                const float4 fk = *reinterpret_cast<const float4*>(k + base);
                const float4 fv = *reinterpret_cast<const float4*>(v + base);
                const int d = ch * 4;
                Kt[(d + 0) * ST + j] = fk.x;
                Kt[(d + 1) * ST + j] = fk.y;
                Kt[(d + 2) * ST + j] = fk.z;
                Kt[(d + 3) * ST + j] = fk.w;
                *reinterpret_cast<float4*>(&Vs[j * ST + ch * 4]) = fv;
            }
        }
        __syncthreads();

        // ---- S = Q K^T : 4x4 micro-tile per thread ----
        float s[4][4];
        #pragma unroll
        for (int r = 0; r < 4; r++)
            #pragma unroll
            for (int c = 0; c < 4; c++) s[r][c] = 0.0f;

        #pragma unroll 16
        for (int d = 0; d < DD; d++) {
            const float4 q4 = *reinterpret_cast<const float4*>(&Qt[d * ST + 4 * ty]);
            const float4 k4 = *reinterpret_cast<const float4*>(&Kt[d * ST + 4 * tx]);
            const float qa[4] = {q4.x, q4.y, q4.z, q4.w};
            const float ka[4] = {k4.x, k4.y, k4.z, k4.w};
            #pragma unroll
            for (int r = 0; r < 4; r++)
                #pragma unroll
                for (int c = 0; c < 4; c++)
                    s[r][c] = fmaf(qa[r], ka[c], s[r][c]);
        }

        // ---- online softmax (base-2 domain) ----
        #pragma unroll
        for (int r = 0; r < 4; r++) {
            #pragma unroll
            for (int c = 0; c < 4; c++) s[r][c] *= kScale;

            float mt = fmaxf(fmaxf(s[r][0], s[r][1]), fmaxf(s[r][2], s[r][3]));
            #pragma unroll
            for (int off = 1; off < 16; off <<= 1)
                mt = fmaxf(mt, __shfl_xor_sync(0xffffffffu, mt, off, 16));

            const float mn = fmaxf(m[r], mt);
            const float alpha = ex2f(m[r] - mn);
            m[r] = mn;

            float ps = 0.0f;
            #pragma unroll
            for (int c = 0; c < 4; c++) {
                s[r][c] = ex2f(s[r][c] - mn);
                ps += s[r][c];
            }
            #pragma unroll
            for (int off = 1; off < 16; off <<= 1)
                ps += __shfl_xor_sync(0xffffffffu, ps, off, 16);

            l[r] = l[r] * alpha + ps;
            #pragma unroll
            for (int c = 0; c < 4; c++) o[r][c] *= alpha;

            *reinterpret_cast<float4*>(&Ps[(4 * ty + r) * ST + 4 * tx]) =
                make_float4(s[r][0], s[r][1], s[r][2], s[r][3]);
        }
        __syncthreads();   // Ps visible to all; Kt reads done

        // ---- O += P V ----
        for (int j0 = 0; j0 < BC; j0 += 4) {
            float4 p4[4], v4[4];
            #pragma unroll
            for (int r = 0; r < 4; r++)
                p4[r] = *reinterpret_cast<const float4*>(&Ps[(4 * ty + r) * ST + j0]);
            #pragma unroll
            for (int u = 0; u < 4; u++)
                v4[u] = *reinterpret_cast<const float4*>(&Vs[(j0 + u) * ST + 4 * tx]);

            #pragma unroll
            for (int r = 0; r < 4; r++) {
                const float pa[4] = {p4[r].x, p4[r].y, p4[r].z, p4[r].w};
                #pragma unroll
                for (int u = 0; u < 4; u++) {
                    o[r][0] = fmaf(pa[u], v4[u].x, o[r][0]);
                    o[r][1] = fmaf(pa[u], v4[u].y, o[r][1]);
                    o[r][2] = fmaf(pa[u], v4[u].z, o[r][2]);
                    o[r][3] = fmaf(pa[u], v4[u].w, o[r][3]);
                }
            }
        }
    }

    // ---- epilogue: normalize and store ----
    #pragma unroll
    for (int r = 0; r < 4; r++) {
        const float inv = 1.0f / l[r];
        float4 res;
        res.x = o[r][0] * inv;
        res.y = o[r][1] * inv;
        res.z = o[r][2] * inv;
        res.w = o[r][3] * inv;
        *reinterpret_cast<float4*>(
            out + ((size_t)((b * SS + s0 + 4 * ty + r) * HH + h)) * DD + 4 * tx) = res;
    }
}

extern "C" void kernel_launch(void* const* d_in, const int* in_sizes, int n_in,
                              void* d_out, int out_size) {
    const float* q = (const float*)d_in[0];
    const float* k = (const float*)d_in[1];
    const float* v = (const float*)d_in[2];
    float* out = (float*)d_out;

    const int smem = 4 * DD * ST * (int)sizeof(float);  // 69632 bytes
    cudaFuncSetAttribute(fa_kernel, cudaFuncAttributeMaxDynamicSharedMemorySize, smem);

    dim3 grid(SS / BR, BB * HH);
    fa_kernel<<<grid, 256, smem>>>(q, k, v, out);
}

// round 2
// speedup vs baseline: 1.1748x; 1.1748x over previous
#include <cuda_runtime.h>

#define BB 2
#define SS 4096
#define HH 8
#define DD 64
#define BR 128
#define BC 64
#define ST_V 68
#define ST_P 68

// smem float offsets
#define QT_OFF 0                       // [64][128] swizzled
#define KT_OFF (QT_OFF + 64 * 128)     // [64][64]  swizzled
#define VS_OFF (KT_OFF + 64 * 64)      // [64][ST_V] swizzled d-chunks
#define PS_OFF (VS_OFF + 64 * ST_V)    // [128][ST_P] plain
#define SMEM_FLOATS (PS_OFF + 128 * ST_P)

__device__ __forceinline__ float ex2f(float x) {
    float y;
    asm("ex2.approx.f32 %0, %1;" : "=f"(y) : "f"(x));
    return y;
}

__global__ __launch_bounds__(256, 2)
void fa_kernel(const float* __restrict__ q,
               const float* __restrict__ k,
               const float* __restrict__ v,
               float* __restrict__ out) {
    extern __shared__ float sm[];
    float* Qt = sm + QT_OFF;
    float* Kt = sm + KT_OFF;
    float* Vs = sm + VS_OFF;
    float* Ps = sm + PS_OFF;

    const int t  = threadIdx.x;
    const int tx = t & 15;        // j-group: cols 4tx..4tx+3
    const int ty = t >> 4;        // i-group: rows 8ty..8ty+7
    const int bh = blockIdx.y;
    const int b  = bh >> 3;
    const int h  = bh & 7;
    const int s0 = blockIdx.x * BR;

    const float kScale = 1.44269504088896340736f / 8.0f;  // log2(e)/sqrt(64)

    const int ch = t & 15;        // d-chunk for global loads
    const int r0 = t >> 4;        // row group for global loads

    // ---- load Q tile (128 x 64), pre-scaled, transposed+swizzled into Qt ----
    {
        #pragma unroll
        for (int rr = 0; rr < 8; rr++) {
            const int i = r0 + rr * 16;
            const float4 f = *reinterpret_cast<const float4*>(
                q + ((size_t)((b * SS + s0 + i) * HH + h)) * DD + ch * 4);
            const int ic = i >> 2;
            const int il = i & 3;
            Qt[(4 * ch + 0) * 128 + (((ic ^ ch) & 31) << 2) + il] = f.x * kScale;
            Qt[(4 * ch + 1) * 128 + (((ic ^ ch) & 31) << 2) + il] = f.y * kScale;
            Qt[(4 * ch + 2) * 128 + (((ic ^ ch) & 31) << 2) + il] = f.z * kScale;
            Qt[(4 * ch + 3) * 128 + (((ic ^ ch) & 31) << 2) + il] = f.w * kScale;
        }
    }

    float m[8], l[8], o[8][4];
    #pragma unroll
    for (int r = 0; r < 8; r++) {
        m[r] = -1e30f;
        l[r] = 0.0f;
        #pragma unroll
        for (int c = 0; c < 4; c++) o[r][c] = 0.0f;
    }

    for (int kt = 0; kt < SS / BC; kt++) {
        __syncthreads();   // previous PV done: safe to overwrite Kt/Vs

        // ---- load K (transposed, swizzled) + V (row-major, swizzled chunks) ----
        {
            #pragma unroll
            for (int rr = 0; rr < 4; rr++) {
                const int j = r0 + rr * 16;
                const size_t base =
                    ((size_t)((b * SS + kt * BC + j) * HH + h)) * DD + ch * 4;
                const float4 fk = *reinterpret_cast<const float4*>(k + base);
                const float4 fv = *reinterpret_cast<const float4*>(v + base);
                const int jc = j >> 2;
                const int jl = j & 3;
                Kt[(4 * ch + 0) * 64 + (((jc ^ ch) & 15) << 2) + jl] = fk.x;
                Kt[(4 * ch + 1) * 64 + (((jc ^ ch) & 15) << 2) + jl] = fk.y;
                Kt[(4 * ch + 2) * 64 + (((jc ^ ch) & 15) << 2) + jl] = fk.z;
                Kt[(4 * ch + 3) * 64 + (((jc ^ ch) & 15) << 2) + jl] = fk.w;
                *reinterpret_cast<float4*>(&Vs[j * ST_V + (((ch ^ jc) & 15) << 2)]) = fv;
            }
        }
        __syncthreads();

        // ---- S = Q K^T : 8x4 micro-tile ----
        float s[8][4];
        #pragma unroll
        for (int r = 0; r < 8; r++)
            #pragma unroll
            for (int c = 0; c < 4; c++) s[r][c] = 0.0f;

        #pragma unroll
        for (int d2 = 0; d2 < 16; d2++) {
            const int cq0 = (((2 * ty) ^ d2) & 31) << 2;
            const int cq1 = (((2 * ty + 1) ^ d2) & 31) << 2;
            const int ck  = ((tx ^ d2) & 15) << 2;
            #pragma unroll
            for (int dd = 0; dd < 4; dd++) {
                const int d = 4 * d2 + dd;
                const float4 qa = *reinterpret_cast<const float4*>(&Qt[d * 128 + cq0]);
                const float4 qb = *reinterpret_cast<const float4*>(&Qt[d * 128 + cq1]);
                const float4 k4 = *reinterpret_cast<const float4*>(&Kt[d * 64 + ck]);
                const float qv[8] = {qa.x, qa.y, qa.z, qa.w, qb.x, qb.y, qb.z, qb.w};
                const float kv[4] = {k4.x, k4.y, k4.z, k4.w};
                #pragma unroll
                for (int r = 0; r < 8; r++)
                    #pragma unroll
                    for (int c = 0; c < 4; c++)
                        s[r][c] = fmaf(qv[r], kv[c], s[r][c]);
            }
        }

        // ---- online softmax (base-2; scale pre-folded into Q) ----
        #pragma unroll
        for (int r = 0; r < 8; r++) {
            float mt = fmaxf(fmaxf(s[r][0], s[r][1]), fmaxf(s[r][2], s[r][3]));
            #pragma unroll
            for (int off = 1; off < 16; off <<= 1)
                mt = fmaxf(mt, __shfl_xor_sync(0xffffffffu, mt, off, 16));

            const float mn = fmaxf(m[r], mt);
            const float alpha = ex2f(m[r] - mn);
            m[r] = mn;

            float ps = 0.0f;
            #pragma unroll
            for (int c = 0; c < 4; c++) {
                s[r][c] = ex2f(s[r][c] - mn);
                ps += s[r][c];
            }
            #pragma unroll
            for (int off = 1; off < 16; off <<= 1)
                ps += __shfl_xor_sync(0xffffffffu, ps, off, 16);

            l[r] = l[r] * alpha + ps;
            #pragma unroll
            for (int c = 0; c < 4; c++) o[r][c] *= alpha;

            *reinterpret_cast<float4*>(&Ps[(8 * ty + r) * ST_P + 4 * tx]) =
                make_float4(s[r][0], s[r][1], s[r][2], s[r][3]);
        }
        __syncthreads();   // Ps visible; Kt reads finished

        // ---- O += P V ----
        #pragma unroll 4
        for (int j2 = 0; j2 < 16; j2++) {
            const int cv = ((tx ^ j2) & 15) << 2;
            float4 v4[4];
            #pragma unroll
            for (int u = 0; u < 4; u++)
                v4[u] = *reinterpret_cast<const float4*>(&Vs[(4 * j2 + u) * ST_V + cv]);

            #pragma unroll
            for (int r = 0; r < 8; r++) {
                const float4 p4 = *reinterpret_cast<const float4*>(
                    &Ps[(8 * ty + r) * ST_P + 4 * j2]);
                const float pa[4] = {p4.x, p4.y, p4.z, p4.w};
                #pragma unroll
                for (int u = 0; u < 4; u++) {
                    o[r][0] = fmaf(pa[u], v4[u].x, o[r][0]);
                    o[r][1] = fmaf(pa[u], v4[u].y, o[r][1]);
                    o[r][2] = fmaf(pa[u], v4[u].z, o[r][2]);
                    o[r][3] = fmaf(pa[u], v4[u].w, o[r][3]);
                }
            }
        }
    }

    // ---- epilogue ----
    #pragma unroll
    for (int r = 0; r < 8; r++) {
        const float inv = 1.0f / l[r];
        float4 res;
        res.x = o[r][0] * inv;
        res.y = o[r][1] * inv;
        res.z = o[r][2] * inv;
        res.w = o[r][3] * inv;
        *reinterpret_cast<float4*>(
            out + ((size_t)((b * SS + s0 + 8 * ty + r) * HH + h)) * DD + 4 * tx) = res;
    }
}

extern "C" void kernel_launch(void* const* d_in, const int* in_sizes, int n_in,
                              void* d_out, int out_size) {
    const float* q = (const float*)d_in[0];
    const float* k = (const float*)d_in[1];
    const float* v = (const float*)d_in[2];
    float* out = (float*)d_out;

    const int smem = SMEM_FLOATS * (int)sizeof(float);  // 101376 bytes
    cudaFuncSetAttribute(fa_kernel, cudaFuncAttributeMaxDynamicSharedMemorySize, smem);

    dim3 grid(SS / BR, BB * HH);
    fa_kernel<<<grid, 256, smem>>>(q, k, v, out);
}

// round 3
// speedup vs baseline: 3.4061x; 2.8994x over previous
#include <cuda_runtime.h>
#include <cstdint>

#define BB 2
#define SS 4096
#define HH 8
#define DD 64
#define BR 128
#define BC 64
#define STK 72   // K/V smem row stride (floats): 8 mod 32 -> conflict-free frag reads
#define STP 68   // P smem row stride: 4 mod 32 -> conflict-free B-frag reads

#define KS_OFF 0
#define VS_OFF (KS_OFF + 64 * STK)
#define PS_OFF (VS_OFF + 64 * STK)
#define AL_OFF (PS_OFF + BR * STP)
#define SMEM_FLOATS (AL_OFF + BR)

__device__ __forceinline__ uint32_t f2tf(float x) {
    uint32_t r;
    asm("cvt.rna.tf32.f32 %0, %1;" : "=r"(r) : "f"(x));
    return r;
}
__device__ __forceinline__ float ex2f(float x) {
    float y;
    asm("ex2.approx.f32 %0, %1;" : "=f"(y) : "f"(x));
    return y;
}
__device__ __forceinline__ void mma8(float* c, const uint32_t* a, uint32_t b0, uint32_t b1) {
    asm("mma.sync.aligned.m16n8k8.row.col.f32.tf32.tf32.f32 "
        "{%0,%1,%2,%3}, {%4,%5,%6,%7}, {%8,%9}, {%0,%1,%2,%3};"
        : "+f"(c[0]), "+f"(c[1]), "+f"(c[2]), "+f"(c[3])
        : "r"(a[0]), "r"(a[1]), "r"(a[2]), "r"(a[3]), "r"(b0), "r"(b1));
}

__global__ __launch_bounds__(128, 2)
void fa_kernel(const float* __restrict__ q,
               const float* __restrict__ k,
               const float* __restrict__ v,
               float* __restrict__ out) {
    extern __shared__ float sm[];
    float* Ks = sm + KS_OFF;   // [64][STK] row-major, d pair-reordered
    float* Vs = sm + VS_OFF;   // [64][STK] row-major, d pair-reordered
    float* Ps = sm + PS_OFF;   // [BR][STP] plain
    float* Al = sm + AL_OFF;   // per-row alpha / 1/l

    const int t    = threadIdx.x;
    const int w    = t >> 5;
    const int lane = t & 31;
    const int g    = lane >> 2;
    const int tg   = lane & 3;
    const int bh   = blockIdx.y;
    const int b    = bh >> 3;
    const int h    = bh & 7;
    const int s0   = blockIdx.x * BR;

    const float kScale = 1.44269504088896340736f / 8.0f;  // log2(e)/sqrt(64)

    // ---- Q fragments, resident in registers for the whole kernel ----
    uint32_t qf[2][8][4];
    #pragma unroll
    for (int rb = 0; rb < 2; rb++) {
        const int rlo = s0 + 32 * w + 16 * rb + g;
        const size_t blo = ((size_t)((b * SS + rlo) * HH + h)) * DD;
        const size_t bhi = blo + (size_t)8 * HH * DD;
        #pragma unroll
        for (int kb = 0; kb < 8; kb++) {
            const int c0 = 8 * kb + tg;
            qf[rb][kb][0] = f2tf(q[blo + c0] * kScale);
            qf[rb][kb][1] = f2tf(q[bhi + c0] * kScale);
            qf[rb][kb][2] = f2tf(q[blo + c0 + 4] * kScale);
            qf[rb][kb][3] = f2tf(q[bhi + c0 + 4] * kScale);
        }
    }

    float mrow[2][2], lrow[2][2];
    float o[4][4][4];  // O^T accum: [mb][nbi][reg]; rows d=16mb+{g,g+8}, cols i=32w+8nbi+{2tg,2tg+1}
    #pragma unroll
    for (int rb = 0; rb < 2; rb++) {
        mrow[rb][0] = -1e30f; mrow[rb][1] = -1e30f;
        lrow[rb][0] = 0.0f;   lrow[rb][1] = 0.0f;
    }
    #pragma unroll
    for (int mb = 0; mb < 4; mb++)
        #pragma unroll
        for (int nbi = 0; nbi < 4; nbi++)
            #pragma unroll
            for (int r = 0; r < 4; r++) o[mb][nbi][r] = 0.0f;

    const int ch  = t & 15;   // d-chunk (float4) for K/V tile loads
    const int jr  = t >> 4;   // 0..7
    const int cbk = ch >> 1;
    const int clo = ch & 1;
    const int wd  = ((g & 3) << 1) + ((g >> 2) & 1);  // word(d) within 8-block for d=g

    for (int kt = 0; kt < SS / BC; kt++) {
        __syncthreads();
        // ---- load K/V tile: row-major, (d,d+4)-pair interleaved within 8-blocks ----
        #pragma unroll
        for (int it = 0; it < 8; it++) {
            const int j = jr + 8 * it;
            const size_t base = ((size_t)((b * SS + kt * BC + j) * HH + h)) * DD + ch * 4;
            const float4 fk = *reinterpret_cast<const float4*>(k + base);
            const float4 fv = *reinterpret_cast<const float4*>(v + base);
            float* kr = Ks + j * STK + cbk * 8 + clo;
            float* vr = Vs + j * STK + cbk * 8 + clo;
            kr[0] = __uint_as_float(f2tf(fk.x));
            kr[2] = __uint_as_float(f2tf(fk.y));
            kr[4] = __uint_as_float(f2tf(fk.z));
            kr[6] = __uint_as_float(f2tf(fk.w));
            vr[0] = __uint_as_float(f2tf(fv.x));
            vr[2] = __uint_as_float(f2tf(fv.y));
            vr[4] = __uint_as_float(f2tf(fv.z));
            vr[6] = __uint_as_float(f2tf(fv.w));
        }
        __syncthreads();

        // ---- S = Q K^T (tensor cores) ----
        float s[2][8][4];
        #pragma unroll
        for (int rb = 0; rb < 2; rb++)
            #pragma unroll
            for (int nb = 0; nb < 8; nb++)
                #pragma unroll
                for (int r = 0; r < 4; r++) s[rb][nb][r] = 0.0f;

        #pragma unroll
        for (int kb = 0; kb < 8; kb++) {
            #pragma unroll
            for (int nb = 0; nb < 8; nb++) {
                const float2 bb = *reinterpret_cast<const float2*>(
                    Ks + (8 * nb + g) * STK + kb * 8 + 2 * tg);
                const uint32_t b0 = __float_as_uint(bb.x);
                const uint32_t b1 = __float_as_uint(bb.y);
                mma8(s[0][nb], qf[0][kb], b0, b1);
                mma8(s[1][nb], qf[1][kb], b0, b1);
            }
        }

        // ---- online softmax (base-2); write P (tf32) + per-row alpha to smem ----
        #pragma unroll
        for (int rb = 0; rb < 2; rb++) {
            float mx0 = s[rb][0][0], mx1 = s[rb][0][2];
            #pragma unroll
            for (int nb = 0; nb < 8; nb++) {
                mx0 = fmaxf(mx0, fmaxf(s[rb][nb][0], s[rb][nb][1]));
                mx1 = fmaxf(mx1, fmaxf(s[rb][nb][2], s[rb][nb][3]));
            }
            mx0 = fmaxf(mx0, __shfl_xor_sync(0xffffffffu, mx0, 1));
            mx0 = fmaxf(mx0, __shfl_xor_sync(0xffffffffu, mx0, 2));
            mx1 = fmaxf(mx1, __shfl_xor_sync(0xffffffffu, mx1, 1));
            mx1 = fmaxf(mx1, __shfl_xor_sync(0xffffffffu, mx1, 2));

            const float mn0 = fmaxf(mrow[rb][0], mx0);
            const float mn1 = fmaxf(mrow[rb][1], mx1);
            const float al0 = ex2f(mrow[rb][0] - mn0);
            const float al1 = ex2f(mrow[rb][1] - mn1);
            mrow[rb][0] = mn0; mrow[rb][1] = mn1;

            float sum0 = 0.0f, sum1 = 0.0f;
            const int rlo = 32 * w + 16 * rb + g;
            #pragma unroll
            for (int nb = 0; nb < 8; nb++) {
                const float p0 = ex2f(s[rb][nb][0] - mn0);
                const float p1 = ex2f(s[rb][nb][1] - mn0);
                const float p2 = ex2f(s[rb][nb][2] - mn1);
                const float p3 = ex2f(s[rb][nb][3] - mn1);
                sum0 += p0 + p1;
                sum1 += p2 + p3;
                float2 st0, st1;
                st0.x = __uint_as_float(f2tf(p0));
                st0.y = __uint_as_float(f2tf(p1));
                st1.x = __uint_as_float(f2tf(p2));
                st1.y = __uint_as_float(f2tf(p3));
                *reinterpret_cast<float2*>(Ps + rlo * STP + 8 * nb + 2 * tg) = st0;
                *reinterpret_cast<float2*>(Ps + (rlo + 8) * STP + 8 * nb + 2 * tg) = st1;
            }
            sum0 += __shfl_xor_sync(0xffffffffu, sum0, 1);
            sum0 += __shfl_xor_sync(0xffffffffu, sum0, 2);
            sum1 += __shfl_xor_sync(0xffffffffu, sum1, 1);
            sum1 += __shfl_xor_sync(0xffffffffu, sum1, 2);

            lrow[rb][0] = lrow[rb][0] * al0 + sum0;
            lrow[rb][1] = lrow[rb][1] * al1 + sum1;
            if (tg == 0) {
                Al[rlo]     = al0;
                Al[rlo + 8] = al1;
            }
        }
        __syncwarp();

        // ---- rescale O^T by alpha(i) ----
        #pragma unroll
        for (int nbi = 0; nbi < 4; nbi++) {
            const float ae = Al[32 * w + 8 * nbi + 2 * tg];
            const float ao = Al[32 * w + 8 * nbi + 2 * tg + 1];
            #pragma unroll
            for (int mb = 0; mb < 4; mb++) {
                o[mb][nbi][0] *= ae; o[mb][nbi][1] *= ao;
                o[mb][nbi][2] *= ae; o[mb][nbi][3] *= ao;
            }
        }

        // ---- O^T += V^T P^T (tensor cores; A=V^T frags, B=P^T frags) ----
        #pragma unroll
        for (int kb = 0; kb < 8; kb++) {
            uint32_t af[4][4];
            const float* vrow0 = Vs + (8 * kb + tg) * STK;
            const float* vrow1 = Vs + (8 * kb + tg + 4) * STK;
            #pragma unroll
            for (int mb = 0; mb < 4; mb++) {
                af[mb][0] = __float_as_uint(vrow0[16 * mb + wd]);       // (d=16mb+g,   j=8kb+tg)
                af[mb][1] = __float_as_uint(vrow0[16 * mb + 8 + wd]);   // (d=16mb+g+8, j=8kb+tg)
                af[mb][2] = __float_as_uint(vrow1[16 * mb + wd]);       // (d=16mb+g,   j=8kb+tg+4)
                af[mb][3] = __float_as_uint(vrow1[16 * mb + 8 + wd]);   // (d=16mb+g+8, j=8kb+tg+4)
            }
            #pragma unroll
            for (int nbi = 0; nbi < 4; nbi++) {
                const int irow = 32 * w + 8 * nbi + g;
                const uint32_t b0 = __float_as_uint(Ps[irow * STP + 8 * kb + tg]);
                const uint32_t b1 = __float_as_uint(Ps[irow * STP + 8 * kb + tg + 4]);
                #pragma unroll
                for (int mb = 0; mb < 4; mb++)
                    mma8(o[mb][nbi], af[mb], b0, b1);
            }
        }
    }

    // ---- epilogue: 1/l via smem (layout change), scale, store ----
    #pragma unroll
    for (int rb = 0; rb < 2; rb++) {
        if (tg == 0) {
            const int rlo = 32 * w + 16 * rb + g;
            Al[rlo]     = 1.0f / lrow[rb][0];
            Al[rlo + 8] = 1.0f / lrow[rb][1];
        }
    }
    __syncwarp();

    #pragma unroll
    for (int nbi = 0; nbi < 4; nbi++) {
        const float le = Al[32 * w + 8 * nbi + 2 * tg];
        const float lo = Al[32 * w + 8 * nbi + 2 * tg + 1];
        const int i0 = s0 + 32 * w + 8 * nbi + 2 * tg;
        float* out0 = out + ((size_t)((b * SS + i0) * HH + h)) * DD;
        float* out1 = out0 + (size_t)HH * DD;
        #pragma unroll
        for (int mb = 0; mb < 4; mb++) {
            const int d0 = 16 * mb + g;
            out0[d0]     = o[mb][nbi][0] * le;
            out0[d0 + 8] = o[mb][nbi][2] * le;
            out1[d0]     = o[mb][nbi][1] * lo;
            out1[d0 + 8] = o[mb][nbi][3] * lo;
        }
    }
}

extern "C" void kernel_launch(void* const* d_in, const int* in_sizes, int n_in,
                              void* d_out, int out_size) {
    const float* q = (const float*)d_in[0];
    const float* k = (const float*)d_in[1];
    const float* v = (const float*)d_in[2];
    float* out = (float*)d_out;

    const int smem = SMEM_FLOATS * (int)sizeof(float);  // 72192 bytes
    cudaFuncSetAttribute(fa_kernel, cudaFuncAttributeMaxDynamicSharedMemorySize, smem);

    dim3 grid(SS / BR, BB * HH);
    fa_kernel<<<grid, 128, smem>>>(q, k, v, out);
}